// round 4
// baseline (speedup 1.0000x reference)
#include <cuda_runtime.h>
#include <cuda_bf16.h>
#include <math.h>

#define MAX_B 32768
__device__ float        g_partial[MAX_B];
__device__ unsigned int g_count;   // atomicInc wraps to 0 each run -> deterministic

__device__ __forceinline__ float log_sigmoid(float x) {
    return fminf(x, 0.0f) - log1pf(__expf(-fabsf(x)));
}

// R1-proven gather layout: one CTA per batch element, 128 threads = one per dim,
// scalar loads, neg indices staged in smem. Fused deterministic tail reduction
// (last-arriving block) replaces the separate reduce kernel.
__global__ void __launch_bounds__(128, 16)
skipgram_fused(const int* __restrict__ target,
               const int* __restrict__ context,
               const int* __restrict__ neg,
               const float* __restrict__ emb,
               float* __restrict__ out,
               int B, int K)
{
    const int b = blockIdx.x;
    const int d = threadIdx.x;           // 0..127
    const int lane = d & 31;
    const int wid  = d >> 5;             // 0..3

    __shared__ int   s_neg[32];
    __shared__ float s_red[8];
    __shared__ int   s_last;

    // Indices: broadcast loads + smem stage for negatives.
    const int t = target[b];
    const int c = context[b];
    if (d < K) s_neg[d] = neg[b * K + d];
    __syncthreads();

    const float v = __ldg(&emb[(long long)t * 128 + d]);
    const float u = __ldg(&emb[(long long)c * 128 + d]);

    // sum_k dot(u_k, v) == dot(sum_k u_k, v): elementwise row sum, one dot.
    float s = 0.0f;
    #pragma unroll
    for (int k = 0; k < 20; ++k) {
        if (k < K) {
            long long row = (long long)s_neg[k] * 128;
            s += __ldg(&emb[row + d]);
        }
    }

    float pos_p = u * v;
    float neg_p = s * v;

    #pragma unroll
    for (int off = 16; off > 0; off >>= 1) {
        pos_p += __shfl_down_sync(0xffffffffu, pos_p, off);
        neg_p += __shfl_down_sync(0xffffffffu, neg_p, off);
    }
    if (lane == 0) {
        s_red[wid]     = pos_p;
        s_red[wid + 4] = neg_p;
    }
    __syncthreads();

    if (d == 0) {
        float dot_uv = s_red[0] + s_red[1] + s_red[2] + s_red[3];
        float dot_sv = s_red[4] + s_red[5] + s_red[6] + s_red[7];
        g_partial[b] = log_sigmoid(dot_uv) + log_sigmoid(-dot_sv);
        __threadfence();
        unsigned prev = atomicInc(&g_count, (unsigned)(B - 1)); // wraps to 0
        s_last = (prev == (unsigned)(B - 1)) ? 1 : 0;
    }
    __syncthreads();

    // Last-arriving block: deterministic fixed-order reduction of B partials.
    if (s_last) {
        __threadfence();
        float acc = 0.0f;
        for (int i = d; i < B; i += 128)
            acc += g_partial[i];
        #pragma unroll
        for (int off = 16; off > 0; off >>= 1)
            acc += __shfl_down_sync(0xffffffffu, acc, off);
        if (lane == 0) s_red[wid] = acc;
        __syncthreads();
        if (d == 0)
            out[0] = -(s_red[0] + s_red[1] + s_red[2] + s_red[3]) / (float)B;
    }
}

extern "C" void kernel_launch(void* const* d_in, const int* in_sizes, int n_in,
                              void* d_out, int out_size)
{
    const int*   target  = (const int*)d_in[0];
    const int*   context = (const int*)d_in[1];
    const int*   neg     = (const int*)d_in[2];
    const float* emb     = (const float*)d_in[3];
    float*       out     = (float*)d_out;

    const int B = in_sizes[0];
    const int K = in_sizes[2] / B;   // 20

    skipgram_fused<<<B, 128>>>(target, context, neg, emb, out, B, K);
}

// round 5
// speedup vs baseline: 1.3478x; 1.3478x over previous
#include <cuda_runtime.h>
#include <cuda_bf16.h>
#include <math.h>

#define ELEMS_PER_CTA 8
#define MAX_BLOCKS 8192

__device__ float        g_partial[MAX_BLOCKS];
__device__ unsigned int g_count;   // atomicInc wraps to 0 each run -> deterministic

__device__ __forceinline__ float log_sigmoid(float x) {
    return fminf(x, 0.0f) - log1pf(__expf(-fabsf(x)));
}

// R1-proven gather: 128 threads = one per dim, scalar LDG.32 per row so each
// warp-load is one coalesced 128B line. Each CTA handles 8 consecutive batch
// elements -> grid 2048, making the fused deterministic tail (last-arriving
// block) nearly free (2048 same-address atomics ~= 1us).
__global__ void __launch_bounds__(128, 16)
skipgram_fused(const int* __restrict__ target,
               const int* __restrict__ context,
               const int* __restrict__ neg,
               const float* __restrict__ emb,
               float* __restrict__ out,
               int B, int K, int nblocks)
{
    const int d    = threadIdx.x;        // 0..127 (embedding dim)
    const int lane = d & 31;
    const int wid  = d >> 5;             // 0..3

    __shared__ float s_red[8];
    __shared__ int   s_last;

    float acc = 0.0f;                    // thread 0 only

    const int b0 = blockIdx.x * ELEMS_PER_CTA;

    #pragma unroll 1
    for (int e = 0; e < ELEMS_PER_CTA; ++e) {
        const int b = b0 + e;
        if (b < B) {
            // Per-warp index fetch (no block sync needed before gathers).
            const int t = target[b];
            const int c = context[b];
            int my_neg = (lane < K) ? neg[b * K + lane] : 0;

            const float v = __ldg(&emb[(long long)t * 128 + d]);
            const float u = __ldg(&emb[(long long)c * 128 + d]);

            // sum_k dot(u_k, v) == dot(sum_k u_k, v)
            float s = 0.0f;
            if (K == 20) {
                #pragma unroll
                for (int k = 0; k < 20; ++k) {
                    int idx = __shfl_sync(0xffffffffu, my_neg, k);
                    s += __ldg(&emb[(long long)idx * 128 + d]);
                }
            } else {
                for (int k = 0; k < K; ++k) {
                    int idx = (k < 32) ? __shfl_sync(0xffffffffu, my_neg, k)
                                       : neg[b * K + k];
                    s += __ldg(&emb[(long long)idx * 128 + d]);
                }
            }

            float pos_p = u * v;
            float neg_p = s * v;

            #pragma unroll
            for (int off = 16; off > 0; off >>= 1) {
                pos_p += __shfl_down_sync(0xffffffffu, pos_p, off);
                neg_p += __shfl_down_sync(0xffffffffu, neg_p, off);
            }
            if (lane == 0) {
                s_red[wid]     = pos_p;
                s_red[wid + 4] = neg_p;
            }
        }
        __syncthreads();
        if (d == 0 && b < B) {
            float dot_uv = s_red[0] + s_red[1] + s_red[2] + s_red[3];
            float dot_sv = s_red[4] + s_red[5] + s_red[6] + s_red[7];
            acc += log_sigmoid(dot_uv) + log_sigmoid(-dot_sv);
        }
        __syncthreads();   // protect s_red reuse next iteration
    }

    if (d == 0) {
        g_partial[blockIdx.x] = acc;
        __threadfence();
        unsigned prev = atomicInc(&g_count, (unsigned)(nblocks - 1)); // wraps to 0
        s_last = (prev == (unsigned)(nblocks - 1)) ? 1 : 0;
    }
    __syncthreads();

    // Last-arriving block reduces all partials in fixed order.
    if (s_last) {
        __threadfence();
        float a = 0.0f;
        for (int i = d; i < nblocks; i += 128)
            a += g_partial[i];
        #pragma unroll
        for (int off = 16; off > 0; off >>= 1)
            a += __shfl_down_sync(0xffffffffu, a, off);
        if (lane == 0) s_red[wid] = a;
        __syncthreads();
        if (d == 0)
            out[0] = -(s_red[0] + s_red[1] + s_red[2] + s_red[3]) / (float)B;
    }
}

extern "C" void kernel_launch(void* const* d_in, const int* in_sizes, int n_in,
                              void* d_out, int out_size)
{
    const int*   target  = (const int*)d_in[0];
    const int*   context = (const int*)d_in[1];
    const int*   neg     = (const int*)d_in[2];
    const float* emb     = (const float*)d_in[3];
    float*       out     = (float*)d_out;

    const int B = in_sizes[0];
    const int K = in_sizes[2] / B;   // 20
    const int nblocks = (B + ELEMS_PER_CTA - 1) / ELEMS_PER_CTA;  // 2048

    skipgram_fused<<<nblocks, 128>>>(target, context, neg, emb, out, B, K, nblocks);
}